// round 9
// baseline (speedup 1.0000x reference)
#include <cuda_runtime.h>
#include <cstdint>

#define EMBED 2048
#define KVDIM 512
#define SEQ   2048
#define BATCH 2
#define ROWS_TOTAL 4096

// -------- scratch (allocation-free: __device__ globals), all tf32-as-u32 ----
__device__ uint32_t g_xt [ROWS_TOTAL * EMBED];
__device__ uint32_t g_Wqt[EMBED * EMBED];
__device__ uint32_t g_Wkt[EMBED * KVDIM];
__device__ uint32_t g_Wvt[EMBED * KVDIM];
__device__ uint32_t g_Wot[EMBED * EMBED];
__device__ uint32_t g_Qt [ROWS_TOTAL * EMBED];
__device__ uint32_t g_Kt [ROWS_TOTAL * KVDIM];
__device__ uint32_t g_Vt [ROWS_TOTAL * KVDIM];
__device__ uint32_t g_AOt[ROWS_TOTAL * EMBED];

__device__ __forceinline__ uint32_t f2tf32(float f) {
    uint32_t u;
    asm("cvt.rna.tf32.f32 %0, %1;" : "=r"(u) : "f"(f));
    return u;
}

__device__ __forceinline__ void mma_tf32(float* c, const uint32_t* a, const uint32_t* b) {
    asm volatile(
        "mma.sync.aligned.m16n8k8.row.col.f32.tf32.tf32.f32 "
        "{%0,%1,%2,%3}, {%4,%5,%6,%7}, {%8,%9}, {%0,%1,%2,%3};"
        : "+f"(c[0]), "+f"(c[1]), "+f"(c[2]), "+f"(c[3])
        : "r"(a[0]), "r"(a[1]), "r"(a[2]), "r"(a[3]), "r"(b[0]), "r"(b[1]));
}

__device__ __forceinline__ void cp_async16(uint32_t saddr, const void* g) {
    asm volatile("cp.async.cg.shared.global [%0], [%1], 16;\n" :: "r"(saddr), "l"(g));
}
__device__ __forceinline__ void cp_commit() { asm volatile("cp.async.commit_group;\n"); }
template<int N> __device__ __forceinline__ void cp_wait() {
    asm volatile("cp.async.wait_group %0;\n" :: "n"(N));
}

// ==================== fp32 -> tf32 conversion (memory-bound) ====================
__global__ void cvt_tf32_kernel(const float* __restrict__ in, uint32_t* __restrict__ out) {
    int i = (blockIdx.x * 256 + threadIdx.x) * 4;
    float4 v = *(const float4*)(in + i);
    uint4 o;
    o.x = f2tf32(v.x); o.y = f2tf32(v.y); o.z = f2tf32(v.z); o.w = f2tf32(v.w);
    *(uint4*)(out + i) = o;
}

// ==================== TF32 GEMM (preconverted inputs, cp.async 3-stage) =========
// 128x128x32 block tile, 256 thr = 8 warps (2m x 4n), warp 64x32, m16n8k8.
// As[128][36] m-major, Bs[32][136] k-major, per stage. 3 stages.
// __launch_bounds__(256,2): 2 CTAs/SM (2x107.5KB smem = 215KB <= 228KB carveout).
#define GS_A (128 * 36)            // 4608 u32
#define GS_B (32 * 136)            // 4352 u32
#define G_STAGE (GS_A + GS_B)      // 8960 u32
#define G_SMEM_BYTES (3 * G_STAGE * 4)   // 107520 B

__device__ __forceinline__ void gemm_body(
    const uint32_t* __restrict__ A, const uint32_t* __restrict__ B,
    const float* __restrict__ bias, void* __restrict__ Cout,
    int N, int K, int out_tf32, int bm, int bn, uint32_t* sm)
{
    const int tid  = threadIdx.x;
    const int lane = tid & 31;
    const int warp = tid >> 5;
    const int wm   = (warp >> 2) * 64;
    const int wn   = (warp & 3) * 32;
    const int g    = lane >> 2;
    const int tq   = lane & 3;
    const int KT   = K / 32;

    const int a_row = tid >> 3;          // +32*i
    const int a_c4  = (tid & 7) << 2;
    const int b_k   = tid >> 5;          // +8*i
    const int b_n4  = (tid & 31) << 2;

    const uint32_t* aG = A + (size_t)(bm + a_row) * K + a_c4;
    const uint32_t* bG = B + (size_t)b_k * N + bn + b_n4;

    uint32_t sA_base, sB_base;
    {
        uint32_t s0 = (uint32_t)__cvta_generic_to_shared(sm);
        sA_base = s0;
        sB_base = s0 + GS_A * 4;
    }

    float acc[4][4][4];
#pragma unroll
    for (int mt = 0; mt < 4; mt++)
#pragma unroll
        for (int nt = 0; nt < 4; nt++)
#pragma unroll
            for (int i = 0; i < 4; i++) acc[mt][nt][i] = 0.f;

    auto issue = [&](int stage, int kt) {
        uint32_t sa = sA_base + stage * G_STAGE * 4;
        uint32_t sb = sB_base + stage * G_STAGE * 4;
        const uint32_t* ag = aG + kt * 32;
        const uint32_t* bg = bG + (size_t)(kt * 32) * N;
#pragma unroll
        for (int i = 0; i < 4; i++)
            cp_async16(sa + ((a_row + i * 32) * 36 + a_c4) * 4,
                       ag + (size_t)(i * 32) * K);
#pragma unroll
        for (int i = 0; i < 4; i++)
            cp_async16(sb + ((b_k + i * 8) * 136 + b_n4) * 4,
                       bg + (size_t)(i * 8) * N);
    };

    issue(0, 0); cp_commit();
    issue(1, 1); cp_commit();

    for (int kt = 0; kt < KT; kt++) {
        cp_wait<1>();
        __syncthreads();
        if (kt + 2 < KT) issue((kt + 2) % 3, kt + 2);
        cp_commit();

        const uint32_t* Ab = sm + (kt % 3) * G_STAGE + (wm + g) * 36;
        const uint32_t* Bb = sm + (kt % 3) * G_STAGE + GS_A + wn + g;
#pragma unroll
        for (int ks = 0; ks < 4; ks++) {
            uint32_t af[4][4], bf[4][2];
#pragma unroll
            for (int mt = 0; mt < 4; mt++) {
                const uint32_t* p = Ab + mt * 16 * 36 + ks * 8 + tq;
                af[mt][0] = p[0];
                af[mt][1] = p[8 * 36];
                af[mt][2] = p[4];
                af[mt][3] = p[8 * 36 + 4];
            }
#pragma unroll
            for (int nt = 0; nt < 4; nt++) {
                const uint32_t* p = Bb + (ks * 8 + tq) * 136 + nt * 8;
                bf[nt][0] = p[0];
                bf[nt][1] = p[4 * 136];
            }
#pragma unroll
            for (int mt = 0; mt < 4; mt++)
#pragma unroll
                for (int nt = 0; nt < 4; nt++)
                    mma_tf32(acc[mt][nt], af[mt], bf[nt]);
        }
        __syncthreads();
    }

#pragma unroll
    for (int nt = 0; nt < 4; nt++) {
        int n0 = bn + wn + nt * 8 + tq * 2;
        float bv0 = bias[n0], bv1 = bias[n0 + 1];
#pragma unroll
        for (int mt = 0; mt < 4; mt++) {
            int m0 = bm + wm + mt * 16 + g;
            float v00 = acc[mt][nt][0] + bv0, v01 = acc[mt][nt][1] + bv1;
            float v10 = acc[mt][nt][2] + bv0, v11 = acc[mt][nt][3] + bv1;
            if (out_tf32) {
                uint32_t* C = (uint32_t*)Cout;
                *(uint2*)(C + (size_t)m0 * N + n0)       = make_uint2(f2tf32(v00), f2tf32(v01));
                *(uint2*)(C + (size_t)(m0 + 8) * N + n0) = make_uint2(f2tf32(v10), f2tf32(v11));
            } else {
                float* C = (float*)Cout;
                *(float2*)(C + (size_t)m0 * N + n0)       = make_float2(v00, v01);
                *(float2*)(C + (size_t)(m0 + 8) * N + n0) = make_float2(v10, v11);
            }
        }
    }
}

__global__ __launch_bounds__(256, 2) void gemm_tf32(
    const uint32_t* __restrict__ A, const uint32_t* __restrict__ B,
    const float* __restrict__ bias, void* __restrict__ C,
    int N, int K, int out_tf32)
{
    extern __shared__ uint32_t sm[];
    gemm_body(A, B, bias, C, N, K, out_tf32, blockIdx.y * 128, blockIdx.x * 128, sm);
}

__global__ __launch_bounds__(256, 2) void gemm_kv(
    const uint32_t* __restrict__ A,
    const uint32_t* __restrict__ Bk, const float* __restrict__ bk, uint32_t* Ck,
    const uint32_t* __restrict__ Bv, const float* __restrict__ bv, uint32_t* Cv)
{
    extern __shared__ uint32_t sm[];
    const uint32_t* B  = blockIdx.z ? Bv : Bk;
    const float* bias  = blockIdx.z ? bv : bk;
    uint32_t* C        = blockIdx.z ? Cv : Ck;
    gemm_body(A, B, bias, C, KVDIM, EMBED, 1, blockIdx.y * 128, blockIdx.x * 128, sm);
}

// ==================== Flash attention, tf32 mma (causal, GQA) ====================
// 256 thr = 8 warps; q-tile 128 (warp w: rows w*16..+16), k-tile 64, d = 128.
// Each K/V tile now serves 128 q-rows (2x traffic reduction vs q-tile 64),
// and 8 warps/SM hide LDS + mma latency.
#define A_KS_STRIDE 132
#define A_VS_STRIDE 136
#define A_PS_STRIDE 68
#define A_KS_SIZE (64 * A_KS_STRIDE)    // 8448 u32
#define A_VS_SIZE (64 * A_VS_STRIDE)    // 8704 u32
#define A_PS_SIZE (128 * A_PS_STRIDE)   // 8704 u32
#define ATT_SMEM_BYTES ((A_KS_SIZE + A_VS_SIZE + A_PS_SIZE) * 4)  // 103424 B

__global__ __launch_bounds__(256) void gqa_attn_mma(
    const uint32_t* __restrict__ Qt, const uint32_t* __restrict__ Kt,
    const uint32_t* __restrict__ Vt, uint32_t* __restrict__ AOt)
{
    extern __shared__ uint32_t sm[];
    uint32_t* Ks = sm;
    uint32_t* Vs = sm + A_KS_SIZE;
    uint32_t* Ps = Vs + A_VS_SIZE;

    const int tid  = threadIdx.x;
    const int lane = tid & 31;
    const int warp = tid >> 5;
    const int g    = lane >> 2;
    const int tq   = lane & 3;
    const int qb   = 15 - blockIdx.x;       // q-tile of 128 rows; big tiles first
    const int b    = blockIdx.y >> 4;
    const int h    = blockIdx.y & 15;
    const int grp  = h >> 2;
    const float scale = 0.08838834764831845f;

    // ---- stage Q tile (128 tok x 128 d = 4096 uint4) across Ks..Vs region ----
    // (128*132 = 16896 u32 <= Ks+Vs = 17152 u32; overwritten by K/V later)
    const uint32_t* Qg = Qt + (size_t)(b * SEQ + qb * 128) * EMBED + h * 128;
#pragma unroll
    for (int i = 0; i < 16; i++) {
        int idx = i * 256 + tid;
        int tok = idx >> 5, q4 = (idx & 31) << 2;
        *(uint4*)&Ks[tok * A_KS_STRIDE + q4] =
            *(const uint4*)(Qg + (size_t)tok * EMBED + q4);
    }
    __syncthreads();

    uint32_t qf[16][4];
    {
        const uint32_t* base = Ks + (warp * 16 + g) * A_KS_STRIDE + tq;
#pragma unroll
        for (int ks = 0; ks < 16; ks++) {
            qf[ks][0] = base[ks * 8];
            qf[ks][1] = base[ks * 8 + 8 * A_KS_STRIDE];
            qf[ks][2] = base[ks * 8 + 4];
            qf[ks][3] = base[ks * 8 + 8 * A_KS_STRIDE + 4];
        }
    }
    __syncthreads();

    float oacc[16][4];
#pragma unroll
    for (int nt = 0; nt < 16; nt++)
#pragma unroll
        for (int i = 0; i < 4; i++) oacc[nt][i] = 0.f;

    float m0 = -1e30f, m1 = -1e30f, l0 = 0.f, l1 = 0.f;
    const int rowg = qb * 128 + warp * 16 + g;   // global q row (slot g); +8 for slot g+8

    const uint32_t* Kg = Kt + (size_t)(b * SEQ) * KVDIM + grp * 128;
    const uint32_t* Vg = Vt + (size_t)(b * SEQ) * KVDIM + grp * 128;

    const int kb_max = 2 * qb + 1;   // cover cols <= qb*128+127
    for (int kb = 0; kb <= kb_max; kb++) {
        // ---- load K, V tiles (64 tok x 128 d = 2048 uint4 each) ----
#pragma unroll
        for (int i = 0; i < 8; i++) {
            int idx = i * 256 + tid;
            int tok = idx >> 5, q4 = (idx & 31) << 2;
            size_t go = (size_t)(kb * 64 + tok) * KVDIM + q4;
            *(uint4*)&Ks[tok * A_KS_STRIDE + q4] = *(const uint4*)(Kg + go);
            *(uint4*)&Vs[tok * A_VS_STRIDE + q4] = *(const uint4*)(Vg + go);
        }
        __syncthreads();

        // ---- S = Q K^T ----
        float sacc[8][4];
#pragma unroll
        for (int nt = 0; nt < 8; nt++)
#pragma unroll
            for (int i = 0; i < 4; i++) sacc[nt][i] = 0.f;

#pragma unroll
        for (int ks = 0; ks < 16; ks++) {
            const uint32_t* bp = Ks + g * A_KS_STRIDE + ks * 8 + tq;
#pragma unroll
            for (int nt = 0; nt < 8; nt++) {
                uint32_t bf[2];
                bf[0] = bp[nt * 8 * A_KS_STRIDE];
                bf[1] = bp[nt * 8 * A_KS_STRIDE + 4];
                mma_tf32(sacc[nt], qf[ks], bf);
            }
        }

        // ---- online softmax (rows rowg and rowg+8) ----
        const int tile_hi = kb * 64 + 63;
        const bool dg0 = tile_hi > rowg;
        const bool dg1 = tile_hi > rowg + 8;
        const int col0 = kb * 64 + 2 * tq;
        float mx0 = -1e30f, mx1 = -1e30f;
#pragma unroll
        for (int nt = 0; nt < 8; nt++) {
#pragma unroll
            for (int j = 0; j < 2; j++) {
                int col = col0 + nt * 8 + j;
                float v = sacc[nt][j] * scale;
                if (dg0 && col > rowg) v = -1e30f;
                sacc[nt][j] = v;
                mx0 = fmaxf(mx0, v);
                float w = sacc[nt][2 + j] * scale;
                if (dg1 && col > rowg + 8) w = -1e30f;
                sacc[nt][2 + j] = w;
                mx1 = fmaxf(mx1, w);
            }
        }
#pragma unroll
        for (int off = 1; off <= 2; off <<= 1) {
            mx0 = fmaxf(mx0, __shfl_xor_sync(0xffffffffu, mx0, off));
            mx1 = fmaxf(mx1, __shfl_xor_sync(0xffffffffu, mx1, off));
        }
        float nm0 = fmaxf(m0, mx0), nm1 = fmaxf(m1, mx1);
        float c0 = __expf(m0 - nm0), c1 = __expf(m1 - nm1);
        m0 = nm0; m1 = nm1;

        float s0 = 0.f, s1 = 0.f;
#pragma unroll
        for (int nt = 0; nt < 8; nt++) {
#pragma unroll
            for (int j = 0; j < 2; j++) {
                float p = __expf(sacc[nt][j] - nm0);
                sacc[nt][j] = p; s0 += p;
                float q = __expf(sacc[nt][2 + j] - nm1);
                sacc[nt][2 + j] = q; s1 += q;
            }
        }
#pragma unroll
        for (int off = 1; off <= 2; off <<= 1) {
            s0 += __shfl_xor_sync(0xffffffffu, s0, off);
            s1 += __shfl_xor_sync(0xffffffffu, s1, off);
        }
        l0 = l0 * c0 + s0;
        l1 = l1 * c1 + s1;
#pragma unroll
        for (int nt = 0; nt < 16; nt++) {
            oacc[nt][0] *= c0; oacc[nt][1] *= c0;
            oacc[nt][2] *= c1; oacc[nt][3] *= c1;
        }

        // ---- P -> smem as tf32 ----
        {
            uint32_t* pp = Ps + (warp * 16 + g) * A_PS_STRIDE + 2 * tq;
#pragma unroll
            for (int nt = 0; nt < 8; nt++) {
                *(uint2*)&pp[nt * 8] =
                    make_uint2(f2tf32(sacc[nt][0]), f2tf32(sacc[nt][1]));
                *(uint2*)&pp[nt * 8 + 8 * A_PS_STRIDE] =
                    make_uint2(f2tf32(sacc[nt][2]), f2tf32(sacc[nt][3]));
            }
        }
        __syncwarp();   // Ps rows are warp-private

        // ---- O += P V ----
#pragma unroll
        for (int ks = 0; ks < 8; ks++) {
            uint32_t af[4];
            const uint32_t* ap = Ps + (warp * 16 + g) * A_PS_STRIDE + ks * 8 + tq;
            af[0] = ap[0];
            af[1] = ap[8 * A_PS_STRIDE];
            af[2] = ap[4];
            af[3] = ap[8 * A_PS_STRIDE + 4];
            const uint32_t* vp = Vs + (ks * 8 + tq) * A_VS_STRIDE + g;
#pragma unroll
            for (int nt = 0; nt < 16; nt++) {
                uint32_t bf[2];
                bf[0] = vp[nt * 8];
                bf[1] = vp[nt * 8 + 4 * A_VS_STRIDE];
                mma_tf32(oacc[nt], af, bf);
            }
        }
        __syncthreads();
    }

    // ---- epilogue: normalize, cvt to tf32, store AO ----
    float inv0 = 1.f / l0, inv1 = 1.f / l1;
    uint32_t* out0 = AOt + (size_t)(b * SEQ + qb * 128 + warp * 16 + g) * EMBED
                         + h * 128 + 2 * tq;
    uint32_t* out1 = out0 + (size_t)8 * EMBED;
#pragma unroll
    for (int nt = 0; nt < 16; nt++) {
        *(uint2*)(out0 + nt * 8) =
            make_uint2(f2tf32(oacc[nt][0] * inv0), f2tf32(oacc[nt][1] * inv0));
        *(uint2*)(out1 + nt * 8) =
            make_uint2(f2tf32(oacc[nt][2] * inv1), f2tf32(oacc[nt][3] * inv1));
    }
}

// ==================== launch ====================
extern "C" void kernel_launch(void* const* d_in, const int* in_sizes, int n_in,
                              void* d_out, int out_size)
{
    const float* x  = (const float*)d_in[0];
    const float* Wq = (const float*)d_in[1];
    const float* bq = (const float*)d_in[2];
    const float* Wk = (const float*)d_in[3];
    const float* bk = (const float*)d_in[4];
    const float* Wv = (const float*)d_in[5];
    const float* bv = (const float*)d_in[6];
    const float* Wo = (const float*)d_in[7];
    const float* bo = (const float*)d_in[8];
    float* out = (float*)d_out;

    uint32_t *xt, *wqt, *wkt, *wvt, *wot, *qt, *kt, *vt, *aot;
    cudaGetSymbolAddress((void**)&xt,  g_xt);
    cudaGetSymbolAddress((void**)&wqt, g_Wqt);
    cudaGetSymbolAddress((void**)&wkt, g_Wkt);
    cudaGetSymbolAddress((void**)&wvt, g_Wvt);
    cudaGetSymbolAddress((void**)&wot, g_Wot);
    cudaGetSymbolAddress((void**)&qt,  g_Qt);
    cudaGetSymbolAddress((void**)&kt,  g_Kt);
    cudaGetSymbolAddress((void**)&vt,  g_Vt);
    cudaGetSymbolAddress((void**)&aot, g_AOt);

    cudaFuncSetAttribute(gemm_tf32, cudaFuncAttributeMaxDynamicSharedMemorySize,
                         G_SMEM_BYTES);
    cudaFuncSetAttribute(gemm_kv, cudaFuncAttributeMaxDynamicSharedMemorySize,
                         G_SMEM_BYTES);
    cudaFuncSetAttribute(gqa_attn_mma, cudaFuncAttributeMaxDynamicSharedMemorySize,
                         ATT_SMEM_BYTES);

    cvt_tf32_kernel<<<ROWS_TOTAL * EMBED / 1024, 256>>>(x,  xt);
    cvt_tf32_kernel<<<EMBED * EMBED / 1024, 256>>>(Wq, wqt);
    cvt_tf32_kernel<<<EMBED * KVDIM / 1024, 256>>>(Wk, wkt);
    cvt_tf32_kernel<<<EMBED * KVDIM / 1024, 256>>>(Wv, wvt);
    cvt_tf32_kernel<<<EMBED * EMBED / 1024, 256>>>(Wo, wot);

    dim3 blk(256);
    gemm_tf32<<<dim3(EMBED / 128, ROWS_TOTAL / 128), blk, G_SMEM_BYTES>>>(
        xt, wqt, bq, qt, EMBED, EMBED, 1);
    gemm_kv<<<dim3(KVDIM / 128, ROWS_TOTAL / 128, 2), blk, G_SMEM_BYTES>>>(
        xt, wkt, bk, kt, wvt, bv, vt);

    gqa_attn_mma<<<dim3(SEQ / 128, BATCH * 16), dim3(256), ATT_SMEM_BYTES>>>(
        qt, kt, vt, aot);

    gemm_tf32<<<dim3(EMBED / 128, ROWS_TOTAL / 128), blk, G_SMEM_BYTES>>>(
        aot, wot, bo, out, EMBED, EMBED, 0);
}